// round 6
// baseline (speedup 1.0000x reference)
#include <cuda_runtime.h>
#include <cuda_bf16.h>

#define BB    8192
#define BLK   512
#define GRID  64            // 64 blocks co-resident (1/SM); cheap grid barriers
#define KT    64            // time buckets (uniform [0,1))
#define KR    32            // risk buckets (range [-4, 4))
#define CAPT  256           // slots per time bucket (mean 128, +11 sigma)
#define CAPR  48            // slots per (time,risk) cell (mean ~13 max, +10 sigma)

__device__ float2   g_tb[KT * CAPT];      // {t, r} grouped by time-bucket (diagonal)
__device__ int      g_tcnt[KT];
__device__ float    g_mr[KT * KR * CAPR]; // member risks per (tb, rb) cell
__device__ int      g_rcnt[KT * KR];
__device__ float    g_rsum[KT * KR];      // per-cell risk sum (float atomics)
__device__ float2   g_P[KT * KR];         // exclusive prefix over rb: {cnt, sum}
__device__ int      g_tbase[KT + 1];
__device__ float2   g_ev[BB];             // compacted events {t_i, 1+r_i}
__device__ int      g_nev;
__device__ unsigned g_bar1, g_bar2, g_done;
__device__ float    g_ps[GRID];
__device__ int      g_pc[GRID];

__device__ __forceinline__ int bkt_t(float t) {
    int b = (int)(t * (float)KT);
    return min(max(b, 0), KT - 1);
}
__device__ __forceinline__ int bkt_r(float x) {
    int q = (int)((x + 4.0f) * 4.0f);     // monotone non-decreasing
    return min(max(q, 0), KR - 1);
}

__device__ __forceinline__ void gbar(unsigned* c, int tid) {
    __syncthreads();
    if (tid == 0) {
        __threadfence();
        atomicAdd(c, 1u);                              // RED (result unused)
        while (*(volatile unsigned*)c < (unsigned)GRID) { }
        __threadfence();
    }
    __syncthreads();
}

__global__ void __launch_bounds__(BLK, 2) k_fused(const float* __restrict__ risk,
                                                  const float* __restrict__ tm,
                                                  const int*   __restrict__ ev,
                                                  float*       __restrict__ out) {
    const int tid = threadIdx.x;
    const int bid = blockIdx.x;

    __shared__ int hist[KT], spos[KT], sbase[KT];

    // ================= Phase A: scatter (blocks 0..15) =================
    if (tid < KT) { hist[tid] = 0; spos[tid] = 0; }
    __syncthreads();

    float t = 0.f, r = 0.f;
    int   e = 0, b = 0;
    const bool act = (bid < BB / BLK);
    if (act) {
        int i = bid * BLK + tid;
        t = tm[i]; r = risk[i]; e = ev[i];
        b = bkt_t(t);
        atomicAdd(&hist[b], 1);
    }
    __syncthreads();
    if (act && tid < KT && hist[tid] > 0)
        sbase[tid] = atomicAdd(&g_tcnt[tid], hist[tid]);
    __syncthreads();
    if (act) {
        // time-bucket scatter
        int p = sbase[b] + atomicAdd(&spos[b], 1);
        g_tb[b * CAPT + min(p, CAPT - 1)] = make_float2(t, r);
        // risk-cell scatter
        int cell = b * KR + bkt_r(r);
        int m = atomicAdd(&g_rcnt[cell], 1);
        g_mr[cell * CAPR + min(m, CAPR - 1)] = r;
        atomicAdd(&g_rsum[cell], r);
        // event compaction (warp-aggregated)
        unsigned msk = __ballot_sync(0xffffffffu, e == 1);
        int ebase = 0;
        if ((tid & 31) == 0 && msk) ebase = atomicAdd(&g_nev, __popc(msk));
        ebase = __shfl_sync(0xffffffffu, ebase, 0);
        if (e == 1) {
            int q = ebase + __popc(msk & ((1u << (tid & 31)) - 1u));
            g_ev[q] = make_float2(t, 1.0f + r);
        }
    }
    gbar(&g_bar1, tid);

    // ============ Phase B: prefix tables (blocks 0..63 + tbase) ============
    if (bid < KT && tid == 0) {
        float c = 0.f, s = 0.f;
        int row = bid * KR;
        for (int q = 0; q < KR; q++) {
            g_P[row + q] = make_float2(c, s);             // EXCLUSIVE prefix
            c += (float)g_rcnt[row + q];
            s += g_rsum[row + q];
        }
    }
    if (bid == 0 && tid == 32) {
        int a = 0;
        for (int x = 0; x < KT; x++) { g_tbase[x] = a; a += g_tcnt[x]; }
        g_tbase[KT] = a;
    }
    gbar(&g_bar2, tid);

    // ================= Phase D: per-(event, bucket) tasks =================
    __shared__ float2 sP[KT * KR];     // 16 KB
    __shared__ int    sRc[KT * KR];    // 8 KB
    __shared__ int    sTb[KT + 1], sTc[KT];
    for (int k = tid; k < KT * KR; k += BLK) { sP[k] = g_P[k]; sRc[k] = g_rcnt[k]; }
    if (tid <= KT) sTb[tid] = g_tbase[tid];
    if (tid <  KT) sTc[tid] = g_tcnt[tid];
    __syncthreads();

    const int nev = g_nev;
    const int tasks = nev << 6;                            // nev * KT
    float ls0 = 0.f, ls1 = 0.f;
    int   lc  = 0;

    for (int idx = bid * BLK + tid; idx < tasks; idx += GRID * BLK) {
        int en = idx >> 6;
        int tb = idx & (KT - 1);
        float2 E = g_ev[en];
        float ti = E.x, ci = E.y;
        int bi = bkt_t(ti);
        if (tb < bi) continue;

        if (tb > bi) {
            // fully-valid time bucket: analytic below-cells + boundary-cell scan
            int cell = tb * KR + bkt_r(ci);
            float2 P = sP[cell];
            ls0 = fmaf(ci, P.x, ls0) - P.y;
            int m = min(sRc[cell], CAPR);
            const float* mp = &g_mr[cell * CAPR];
            for (int k = 0; k < m; k++)
                ls1 += fmaxf(ci - mp[k], 0.f);
        } else {
            // diagonal bucket: exact time compare; plus analytic cross count
            lc += BB - sTb[bi + 1];
            int n = min(sTc[bi], CAPT);
            const float2* tp = &g_tb[bi * CAPT];
            for (int k = 0; k < n; k++) {
                float2 p = tp[k];
                if (ti < p.x) { lc++; ls1 += fmaxf(ci - p.y, 0.f); }
            }
        }
    }

    // ================= reduce =================
    float lsum = ls0 + ls1;
    #pragma unroll
    for (int o = 16; o; o >>= 1) {
        lsum += __shfl_down_sync(0xffffffffu, lsum, o);
        lc   += __shfl_down_sync(0xffffffffu, lc, o);
    }
    __shared__ float ws[BLK / 32];
    __shared__ int   wc[BLK / 32];
    if ((tid & 31) == 0) { ws[tid >> 5] = lsum; wc[tid >> 5] = lc; }
    __syncthreads();
    if (tid == 0) {
        float s = 0.f; int c = 0;
        #pragma unroll
        for (int k = 0; k < BLK / 32; k++) { s += ws[k]; c += wc[k]; }
        g_ps[bid] = s;
        g_pc[bid] = c;
    }

    __shared__ int amLast;
    if (tid == 0) {
        __threadfence();
        amLast = (atomicAdd(&g_done, 1u) == GRID - 1);
    }
    __syncthreads();

    if (amLast) {
        __threadfence();
        double s = 0.0, c = 0.0;
        for (int i = tid; i < GRID; i += BLK) {
            s += (double)g_ps[i];
            c += (double)g_pc[i];
        }
        #pragma unroll
        for (int o = 16; o; o >>= 1) {
            s += __shfl_down_sync(0xffffffffu, s, o);
            c += __shfl_down_sync(0xffffffffu, c, o);
        }
        __shared__ double fs[BLK / 32], fc[BLK / 32];
        if ((tid & 31) == 0) { fs[tid >> 5] = s; fc[tid >> 5] = c; }
        __syncthreads();
        if (tid == 0) {
            double S = 0.0, C = 0.0;
            #pragma unroll
            for (int k = 0; k < BLK / 32; k++) { S += fs[k]; C += fc[k]; }
            out[0] = (C == 0.0) ? 0.f : (float)(S / C);
        }
        __syncthreads();
        // reset all device state for the next graph replay
        for (int k = tid; k < KT * KR; k += BLK) { g_rcnt[k] = 0; g_rsum[k] = 0.f; }
        for (int k = tid; k < KT; k += BLK) g_tcnt[k] = 0;
        if (tid == 0) { g_nev = 0; g_bar1 = 0; g_bar2 = 0; g_done = 0; }
    }
}

extern "C" void kernel_launch(void* const* d_in, const int* in_sizes, int n_in,
                              void* d_out, int out_size) {
    // metadata order: z (unused), risk, time, event
    const float* risk = (const float*)d_in[1];
    const float* tm   = (const float*)d_in[2];
    const int*   ev   = (const int*)d_in[3];
    float*       out  = (float*)d_out;

    k_fused<<<GRID, BLK>>>(risk, tm, ev, out);
}

// round 7
// speedup vs baseline: 1.6871x; 1.6871x over previous
#include <cuda_runtime.h>
#include <cuda_bf16.h>

#define BB    8192
#define BLK   256
#define GRID  296            // 2/SM resident (required for spin barrier)
#define KT    64             // time buckets, uniform [0,1)
#define CAPJ  192            // j slots/bucket  (mean 128, +5.7 sigma)
#define ECAP  96             // event slots/bucket (mean 64, +4 sigma)
#define IR    4
#define IBLK  (BLK * IR)     // 1024
#define NSLOT (KT * ECAP)    // 6144 virtual event slots
#define NIB   (NSLOT / IBLK) // 6 i-chunks
#define NTILE (NIB * KT)     // 384 tiles

__device__ float2   g_jb[KT * CAPJ];   // {t, r} bucketed rows
__device__ float2   g_eb[KT * ECAP];   // {t, 1+r} bucketed events
__device__ int      g_jcnt[KT], g_ecnt[KT];
__device__ int      g_tick;
__device__ unsigned g_bar, g_done;
__device__ float    g_ps[GRID];
__device__ int      g_pc[GRID];

__device__ __forceinline__ int bkt(float t) {
    int b = (int)(t * (float)KT);
    return min(max(b, 0), KT - 1);
}

__global__ void __launch_bounds__(BLK, 2) k_fused(const float* __restrict__ risk,
                                                  const float* __restrict__ tm,
                                                  const int*   __restrict__ ev,
                                                  float*       __restrict__ out) {
    const int tid = threadIdx.x;
    const int bid = blockIdx.x;

    // ---------------- Phase A: bucket scatter (blocks 0..31) ----------------
    {
        int i = bid * BLK + tid;
        if (i < BB) {
            float t = tm[i];
            float r = risk[i];
            int   b = bkt(t);
            int   p = atomicAdd(&g_jcnt[b], 1);
            g_jb[b * CAPJ + min(p, CAPJ - 1)] = make_float2(t, r);
            if (ev[i] == 1) {
                int q = atomicAdd(&g_ecnt[b], 1);
                g_eb[b * ECAP + min(q, ECAP - 1)] = make_float2(t, 1.0f + r);
            }
        }
    }

    // ---------------- one grid barrier ----------------
    __syncthreads();
    if (tid == 0) {
        __threadfence();
        atomicAdd(&g_bar, 1u);
        while (*(volatile unsigned*)&g_bar < (unsigned)GRID) { }
        __threadfence();
    }
    __syncthreads();

    // stage bucket counts
    __shared__ int sjc[KT], sec[KT];
    if (tid < KT) { sjc[tid] = g_jcnt[tid]; sec[tid] = g_ecnt[tid]; }
    __syncthreads();

    // ---------------- Phase B: ticketed tile loop ----------------
    __shared__ float2 sj[CAPJ];
    __shared__ int    s_t;
    float ls = 0.f, lm = 0.f;
    int   lc = 0;
    const float PINF = __int_as_float(0x7f800000);
    const float NINF = __int_as_float(0xff800000);

    for (;;) {
        __syncthreads();                               // (a) protect s_t / sj
        if (tid == 0) s_t = atomicAdd(&g_tick, 1);
        __syncthreads();                               // (b)
        int tl = s_t;
        if (tl >= NTILE) break;

        int bj  = tl / NIB;          // bj-major: consecutive tickets share bj
        int ic  = tl % NIB;
        int vlo = ic * IBLK;
        int blo = vlo / ECAP;
        int bhi = (vlo + IBLK - 1) / ECAP;
        if (blo > bj) continue;      // whole chunk is time-after bucket bj
        int jn = sjc[bj];
        if (jn == 0) continue;

        // stage j-bucket into smem
        for (int j = tid; j < jn; j += BLK) sj[j] = g_jb[bj * CAPJ + j];
        __syncthreads();                               // (c)

        // load IR event slots into registers
        float ti[IR], ci[IR];
        int   bi[IR];
        #pragma unroll
        for (int k = 0; k < IR; k++) {
            int v  = vlo + k * BLK + tid;
            int be = v / ECAP;
            int pe = v - be * ECAP;
            if (pe < sec[be]) {
                float2 E = g_eb[v];
                ti[k] = E.x; ci[k] = E.y; bi[k] = be;
            } else {
                ti[k] = PINF; ci[k] = NINF; bi[k] = 1 << 28;
            }
        }

        if (bhi < bj) {
            // FULL tile: every (valid) pair valid; invalid slots add exact 0.
            #pragma unroll 4
            for (int j = 0; j < jn; j++) {
                float rj = sj[j].y;
                #pragma unroll
                for (int k = 0; k < IR; k++)
                    ls += fmaxf(ci[k] - rj, 0.f);
            }
        } else {
            // MIXED (diagonal) tile: loop-invariant lane predicates.
            bool fA[IR], fB[IR];
            #pragma unroll
            for (int k = 0; k < IR; k++) { fA[k] = bi[k] < bj; fB[k] = bi[k] == bj; }
            #pragma unroll 2
            for (int j = 0; j < jn; j++) {
                float2 p = sj[j];
                #pragma unroll
                for (int k = 0; k < IR; k++) {
                    bool  tlt = ti[k] < p.x;
                    float h   = fmaxf(ci[k] - p.y, 0.f);
                    if (fA[k] | (fB[k] & tlt)) lm += h;
                    if (fB[k] & tlt)           lc += 1;
                }
            }
        }
    }

    // ---------------- block reduce ----------------
    float lsum = ls + lm;
    #pragma unroll
    for (int o = 16; o; o >>= 1) {
        lsum += __shfl_down_sync(0xffffffffu, lsum, o);
        lc   += __shfl_down_sync(0xffffffffu, lc, o);
    }
    __shared__ float ws[BLK / 32];
    __shared__ int   wc[BLK / 32];
    if ((tid & 31) == 0) { ws[tid >> 5] = lsum; wc[tid >> 5] = lc; }
    __syncthreads();
    if (tid == 0) {
        float s = 0.f; int c = 0;
        #pragma unroll
        for (int k = 0; k < BLK / 32; k++) { s += ws[k]; c += wc[k]; }
        g_ps[bid] = s;
        g_pc[bid] = c;
    }

    // ---------------- last block: final reduce + analytic count ----------------
    __shared__ int amLast;
    if (tid == 0) {
        __threadfence();
        amLast = (atomicAdd(&g_done, 1u) == GRID - 1);
    }
    __syncthreads();

    if (amLast) {
        __threadfence();
        double s = 0.0, c = 0.0;
        for (int i = tid; i < GRID; i += BLK) {
            s += (double)g_ps[i];
            c += (double)g_pc[i];
        }
        #pragma unroll
        for (int o = 16; o; o >>= 1) {
            s += __shfl_down_sync(0xffffffffu, s, o);
            c += __shfl_down_sync(0xffffffffu, c, o);
        }
        __shared__ double fs[BLK / 32], fc[BLK / 32];
        if ((tid & 31) == 0) { fs[tid >> 5] = s; fc[tid >> 5] = c; }
        __syncthreads();
        if (tid == 0) {
            double S = 0.0, C = 0.0;
            #pragma unroll
            for (int k = 0; k < BLK / 32; k++) { S += fs[k]; C += fc[k]; }
            // analytic cross-bucket count: events in be pair with all j in b > be
            long long suf = 0, cross = 0;
            for (int b = KT - 1; b >= 0; b--) {
                cross += (long long)sec[b] * suf;
                suf   += (long long)sjc[b];
            }
            C += (double)cross;
            out[0] = (C == 0.0) ? 0.f : (float)(S / C);
        }
        __syncthreads();
        // reset device state for next graph replay
        if (tid < KT) { g_jcnt[tid] = 0; g_ecnt[tid] = 0; }
        if (tid == 0) { g_tick = 0; g_bar = 0; g_done = 0; }
    }
}

extern "C" void kernel_launch(void* const* d_in, const int* in_sizes, int n_in,
                              void* d_out, int out_size) {
    // metadata order: z (unused), risk, time, event
    const float* risk = (const float*)d_in[1];
    const float* tm   = (const float*)d_in[2];
    const int*   ev   = (const int*)d_in[3];
    float*       out  = (float*)d_out;

    k_fused<<<GRID, BLK>>>(risk, tm, ev, out);
}

// round 8
// speedup vs baseline: 1.9001x; 1.1262x over previous
#include <cuda_runtime.h>
#include <cuda_bf16.h>

#define BB    8192
#define BLK   256
#define GRID  592            // 4 blocks/SM co-resident (spin barrier safe)
#define NQ    4              // time quartiles, fixed cuts 0.25/0.5/0.75
#define JCAP  2304           // j slots/quartile (mean 2048, +6 sigma)
#define ECAP  1280           // event slots/quartile (mean 1024, +8 sigma)
#define IR    5              // IR*BLK = 1280 = ECAP virtual event slots
#define SJMAX 64             // max j-slice length (worst ~40)
#define ROWS_PER_BLK 14      // ceil(8192/592)
#define PINF __int_as_float(0x7f800000)
#define NINF __int_as_float(0xff800000)

__device__ float2   g_jq[NQ * JCAP];   // {t, r} per quartile
__device__ float2   g_eq[NQ * ECAP];   // {t, 1+r} events per quartile
__device__ int      g_jcnt[NQ], g_ecnt[NQ];
__device__ unsigned g_bar, g_done;
__device__ float    g_ps[GRID];
__device__ int      g_pc[GRID];

__global__ void __launch_bounds__(BLK, 4) k_fused(const float* __restrict__ risk,
                                                  const float* __restrict__ tm,
                                                  const int*   __restrict__ ev,
                                                  float*       __restrict__ out) {
    const int tid = threadIdx.x;
    const int bid = blockIdx.x;

    // ======= Phase A: quartile scatter, 14 contiguous rows per block =======
    if (tid < 32) {
        int  i     = bid * ROWS_PER_BLK + tid;
        bool valid = (tid < ROWS_PER_BLK) && (i < BB);
        float t = 0.f, r = 0.f; int e = 0, q = -1;
        if (valid) {
            t = tm[i]; r = risk[i]; e = ev[i];
            q = min(max((int)(t * 4.0f), 0), 3);
        }
        #pragma unroll
        for (int qq = 0; qq < NQ; qq++) {
            unsigned m = __ballot_sync(0xffffffffu, q == qq);
            if (m) {
                int ldr = __ffs(m) - 1, base = 0;
                if (tid == ldr) base = atomicAdd(&g_jcnt[qq], __popc(m));
                base = __shfl_sync(0xffffffffu, base, ldr);
                if (q == qq) {
                    int pos = base + __popc(m & ((1u << tid) - 1u));
                    g_jq[qq * JCAP + min(pos, JCAP - 1)] = make_float2(t, r);
                }
            }
            unsigned me = __ballot_sync(0xffffffffu, (q == qq) && (e == 1));
            if (me) {
                int ldr = __ffs(me) - 1, base = 0;
                if (tid == ldr) base = atomicAdd(&g_ecnt[qq], __popc(me));
                base = __shfl_sync(0xffffffffu, base, ldr);
                if ((q == qq) && (e == 1)) {
                    int pos = base + __popc(me & ((1u << tid) - 1u));
                    g_eq[qq * ECAP + min(pos, ECAP - 1)] = make_float2(t, 1.0f + r);
                }
            }
        }
    }

    // ======= one grid barrier =======
    __syncthreads();
    if (tid == 0) {
        __threadfence();
        atomicAdd(&g_bar, 1u);
        while (*(volatile unsigned*)&g_bar < (unsigned)GRID) { }
        __threadfence();
    }
    __syncthreads();

    __shared__ int sjc[NQ], sec[NQ];
    if (tid < NQ) { sjc[tid] = g_jcnt[tid]; sec[tid] = g_ecnt[tid]; }
    __syncthreads();

    // ======= static block -> (event-quartile ic, j-slice) map =======
    int ic, base, nb;
    if      (bid < 220) { ic = 0; base = 0;   nb = 220; }
    else if (bid < 392) { ic = 1; base = 220; nb = 172; }
    else if (bid < 516) { ic = 2; base = 392; nb = 124; }
    else                { ic = 3; base = 516; nb = 76;  }
    const int sidx = bid - base;

    int cq[NQ + 1];
    cq[0] = 0;
    #pragma unroll
    for (int q = 0; q < NQ; q++) cq[q + 1] = cq[q] + (q >= ic ? sjc[q] : 0);
    const int D  = cq[NQ];                       // j-domain = quartiles ic..3
    const int j0 = (int)((long long)sidx * D / nb);
    const int j1 = (int)((long long)(sidx + 1) * D / nb);
    const int jn = j1 - j0;

    __shared__ float2 sj[SJMAX];
    for (int j = tid; j < jn; j += BLK) {
        int idx = j0 + j;
        int q = ic;
        while (idx >= cq[q + 1]) q++;
        sj[j] = g_jq[q * JCAP + (idx - cq[q])];
    }
    __syncthreads();

    const int nmix = min(max(sjc[ic] - j0, 0), jn);   // MIXED prefix of slice

    // events of quartile ic live in registers for the whole kernel
    float ti[IR], ci[IR];
    {
        const int en = sec[ic];
        #pragma unroll
        for (int k = 0; k < IR; k++) {
            int p = tid + k * BLK;
            if (p < en) { float2 E = g_eq[ic * ECAP + p]; ti[k] = E.x; ci[k] = E.y; }
            else        { ti[k] = PINF; ci[k] = NINF; }
        }
    }

    float ls0 = 0.f, ls1 = 0.f;
    int   lc  = 0;

    // MIXED segment: same-quartile j's, exact time compare + count
    for (int j = 0; j < nmix; j++) {
        float2 p = sj[j];
        #pragma unroll
        for (int k = 0; k < IR; k++) {
            bool  v = ti[k] < p.x;
            float h = fmaxf(ci[k] - p.y, 0.f);
            if (v) { if (k & 1) ls1 += h; else ls0 += h; lc += 1; }
        }
    }
    // FULL segment: strictly later quartiles — no predicate, no count
    #pragma unroll 2
    for (int j = nmix; j < jn; j++) {
        float rj = sj[j].y;
        #pragma unroll
        for (int k = 0; k < IR; k++) {
            float h = fmaxf(ci[k] - rj, 0.f);       // padding ci=-inf -> +0
            if (k & 1) ls1 += h; else ls0 += h;
        }
    }

    // ======= block reduce =======
    float lsum = ls0 + ls1;
    #pragma unroll
    for (int o = 16; o; o >>= 1) {
        lsum += __shfl_down_sync(0xffffffffu, lsum, o);
        lc   += __shfl_down_sync(0xffffffffu, lc, o);
    }
    __shared__ float ws[BLK / 32];
    __shared__ int   wc[BLK / 32];
    if ((tid & 31) == 0) { ws[tid >> 5] = lsum; wc[tid >> 5] = lc; }
    __syncthreads();
    if (tid == 0) {
        float s = 0.f; int c = 0;
        #pragma unroll
        for (int k = 0; k < BLK / 32; k++) { s += ws[k]; c += wc[k]; }
        g_ps[bid] = s;
        g_pc[bid] = c;
    }

    // ======= last block: final reduce + analytic cross count + reset =======
    __shared__ int amLast;
    if (tid == 0) {
        __threadfence();
        amLast = (atomicAdd(&g_done, 1u) == GRID - 1);
    }
    __syncthreads();

    if (amLast) {
        __threadfence();
        double s = 0.0, c = 0.0;
        for (int i = tid; i < GRID; i += BLK) {
            s += (double)g_ps[i];
            c += (double)g_pc[i];
        }
        #pragma unroll
        for (int o = 16; o; o >>= 1) {
            s += __shfl_down_sync(0xffffffffu, s, o);
            c += __shfl_down_sync(0xffffffffu, c, o);
        }
        __shared__ double fs[BLK / 32], fc[BLK / 32];
        if ((tid & 31) == 0) { fs[tid >> 5] = s; fc[tid >> 5] = c; }
        __syncthreads();
        if (tid == 0) {
            double S = 0.0, C = 0.0;
            #pragma unroll
            for (int k = 0; k < BLK / 32; k++) { S += fs[k]; C += fc[k]; }
            // cross-quartile pairs are all valid: t_e < cut <= t_j
            long long suf = 0, cross = 0;
            for (int q = NQ - 1; q >= 0; q--) {
                cross += (long long)sec[q] * suf;
                suf   += (long long)sjc[q];
            }
            C += (double)cross;
            out[0] = (C == 0.0) ? 0.f : (float)(S / C);
        }
        __syncthreads();
        // reset device state for next graph replay
        if (tid < NQ) { g_jcnt[tid] = 0; g_ecnt[tid] = 0; }
        if (tid == 0) { g_bar = 0; g_done = 0; }
    }
}

extern "C" void kernel_launch(void* const* d_in, const int* in_sizes, int n_in,
                              void* d_out, int out_size) {
    // metadata order: z (unused), risk, time, event
    const float* risk = (const float*)d_in[1];
    const float* tm   = (const float*)d_in[2];
    const int*   ev   = (const int*)d_in[3];
    float*       out  = (float*)d_out;

    k_fused<<<GRID, BLK>>>(risk, tm, ev, out);
}

// round 9
// speedup vs baseline: 2.6069x; 1.3720x over previous
#include <cuda_runtime.h>
#include <cuda_bf16.h>

#define BB    8192
#define BLK   288            // 9 warps
#define NIB   4              // i-chunks (fixed)
#define IR    4
#define ICH   (BLK * IR)     // 1152 event slots per chunk; 4*1152=4608 >= nev (11 sigma)
#define JC    64             // j per tile (compile-time -> full unroll)
#define NJC   (BB / JC)      // 128
#define GRID  (NIB * NJC)    // 512 blocks, EXACTLY one tile each
#define NW    (BLK / 32)     // 9 warps
#define PINF  __int_as_float(0x7f800000)
#define NINF  __int_as_float(0xff800000)

__device__ float2   g_ev[BB];        // compacted events {t_i, 1+r_i}
__device__ int      g_nev;
__device__ unsigned g_bar, g_done;
__device__ float    g_ps[GRID];
__device__ int      g_pc[GRID];

__global__ void __launch_bounds__(BLK, 4) k_fused(const float* __restrict__ risk,
                                                  const float* __restrict__ tm,
                                                  const int*   __restrict__ ev,
                                                  float*       __restrict__ out) {
    const int tid  = threadIdx.x;
    const int bid  = blockIdx.x;
    const int lane = tid & 31;
    const int wrp  = tid >> 5;

    // ===== Phase A: block-aggregated event compaction (blocks 0..28) =====
    {
        const int gtid = bid * BLK + tid;
        float t = 0.f, r = 0.f;
        int   e = 0;
        if (gtid < BB) { t = tm[gtid]; r = risk[gtid]; e = ev[gtid]; }

        unsigned m = __ballot_sync(0xffffffffu, e == 1);
        __shared__ int wbase[NW];
        __shared__ int bbase;
        if (lane == 0) wbase[wrp] = __popc(m);
        __syncthreads();
        if (tid == 0) {
            int tot = 0;
            #pragma unroll
            for (int w = 0; w < NW; w++) { int c = wbase[w]; wbase[w] = tot; tot += c; }
            bbase = tot ? atomicAdd(&g_nev, tot) : 0;   // ONE atomic per block
        }
        __syncthreads();
        if (e == 1) {
            int pos = bbase + wbase[wrp] + __popc(m & ((1u << lane) - 1u));
            g_ev[pos] = make_float2(t, 1.0f + r);
        }
    }

    // ===== single grid barrier (512 blocks, 4/SM co-resident) =====
    __syncthreads();
    if (tid == 0) {
        __threadfence();
        atomicAdd(&g_bar, 1u);
        while (*(volatile unsigned*)&g_bar < (unsigned)GRID) { }
        __threadfence();
    }
    __syncthreads();

    const int nev = *(volatile int*)&g_nev;

    // ===== Phase B: exactly ONE (ic, jc) tile per block =====
    const int ic = bid >> 7;          // 0..3
    const int jc = bid & (NJC - 1);   // 0..127
    const int j0 = jc * JC;

    __shared__ float2 sj[JC];
    if (tid < JC) sj[tid] = make_float2(tm[j0 + tid], risk[j0 + tid]);
    __syncthreads();

    float ti[IR], ci[IR];
    #pragma unroll
    for (int k = 0; k < IR; k++) {
        int p = ic * ICH + k * BLK + tid;
        if (p < nev) { float2 E = g_ev[p]; ti[k] = E.x; ci[k] = E.y; }
        else         { ti[k] = PINF; ci[k] = NINF; }
    }

    float ls0 = 0.f, ls1 = 0.f, ls2 = 0.f, ls3 = 0.f;
    int   lc0 = 0,   lc1 = 0;

    #pragma unroll 16
    for (int j = 0; j < JC; j++) {
        float2 p = sj[j];                       // LDS.64 broadcast, serves 4 pairs
        {
            bool  v = ti[0] < p.x;
            float h = fmaxf(ci[0] - p.y, 0.f);
            if (v) { ls0 += h; lc0 += 1; }
        }
        {
            bool  v = ti[1] < p.x;
            float h = fmaxf(ci[1] - p.y, 0.f);
            if (v) { ls1 += h; lc1 += 1; }
        }
        {
            bool  v = ti[2] < p.x;
            float h = fmaxf(ci[2] - p.y, 0.f);
            if (v) { ls2 += h; lc0 += 1; }
        }
        {
            bool  v = ti[3] < p.x;
            float h = fmaxf(ci[3] - p.y, 0.f);
            if (v) { ls3 += h; lc1 += 1; }
        }
    }

    float lsum = (ls0 + ls1) + (ls2 + ls3);
    int   lcnt = lc0 + lc1;

    // ===== block reduce =====
    #pragma unroll
    for (int o = 16; o; o >>= 1) {
        lsum += __shfl_down_sync(0xffffffffu, lsum, o);
        lcnt += __shfl_down_sync(0xffffffffu, lcnt, o);
    }
    __shared__ float ws[NW];
    __shared__ int   wc[NW];
    if (lane == 0) { ws[wrp] = lsum; wc[wrp] = lcnt; }
    __syncthreads();
    if (tid == 0) {
        float s = 0.f; int c = 0;
        #pragma unroll
        for (int k = 0; k < NW; k++) { s += ws[k]; c += wc[k]; }
        g_ps[bid] = s;
        g_pc[bid] = c;
    }

    // ===== last block: final reduce (double) + output + reset =====
    __shared__ int amLast;
    if (tid == 0) {
        __threadfence();
        amLast = (atomicAdd(&g_done, 1u) == GRID - 1);
    }
    __syncthreads();

    if (amLast) {
        __threadfence();
        double s = 0.0, c = 0.0;
        for (int i = tid; i < GRID; i += BLK) {
            s += (double)g_ps[i];
            c += (double)g_pc[i];
        }
        #pragma unroll
        for (int o = 16; o; o >>= 1) {
            s += __shfl_down_sync(0xffffffffu, s, o);
            c += __shfl_down_sync(0xffffffffu, c, o);
        }
        __shared__ double fs[NW], fc[NW];
        if (lane == 0) { fs[wrp] = s; fc[wrp] = c; }
        __syncthreads();
        if (tid == 0) {
            double S = 0.0, C = 0.0;
            #pragma unroll
            for (int k = 0; k < NW; k++) { S += fs[k]; C += fc[k]; }
            out[0] = (C == 0.0) ? 0.f : (float)(S / C);
            g_nev  = 0;        // reset for next graph replay
            g_bar  = 0;
            g_done = 0;
        }
    }
}

extern "C" void kernel_launch(void* const* d_in, const int* in_sizes, int n_in,
                              void* d_out, int out_size) {
    // metadata order: z (unused), risk, time, event
    const float* risk = (const float*)d_in[1];
    const float* tm   = (const float*)d_in[2];
    const int*   ev   = (const int*)d_in[3];
    float*       out  = (float*)d_out;

    k_fused<<<GRID, BLK>>>(risk, tm, ev, out);
}